// round 16
// baseline (speedup 1.0000x reference)
#include <cuda_runtime.h>
#include <cuda_fp16.h>
#include <cstdint>

typedef unsigned long long ull;

#define NB     4
#define NHEADS 4
#define DH     32
#define NTOK   256
#define QCH    256
#define STOT   16384
#define ST     32

// ---------------- device global scratch ----------------
__device__ __align__(16) float g_kt[NB * NHEADS * DH * NTOK];
__device__ __align__(16) float g_vt[NB * NHEADS * DH * NTOK];
__device__ __align__(16) float g_f[(size_t)NB * QCH * STOT];   // gate!=0 path
__device__ __align__(16) __half g_w1h[512 * 256];
__device__ __align__(16) __half g_w2h[256 * 512];

// ---------------- helpers ----------------
__device__ __forceinline__ uint32_t smem_u32(const void* p) {
    uint32_t a;
    asm("{ .reg .u64 t; cvta.to.shared.u64 t, %1; cvt.u32.u64 %0, t; }" : "=r"(a) : "l"(p));
    return a;
}
__device__ __forceinline__ void cp16(uint32_t s, const void* g) {
    asm volatile("cp.async.cg.shared.global [%0], [%1], 16;" :: "r"(s), "l"(g));
}
__device__ __forceinline__ void ldsm4(uint32_t& r0, uint32_t& r1, uint32_t& r2, uint32_t& r3, uint32_t a) {
    asm volatile("ldmatrix.sync.aligned.m8n8.x4.shared.b16 {%0,%1,%2,%3}, [%4];"
        : "=r"(r0), "=r"(r1), "=r"(r2), "=r"(r3) : "r"(a));
}
__device__ __forceinline__ void mma16816(float* c, const uint32_t* a, uint32_t b0, uint32_t b1) {
    asm volatile("mma.sync.aligned.m16n8k16.row.col.f32.f16.f16.f32 "
        "{%0,%1,%2,%3}, {%4,%5,%6,%7}, {%8,%9}, {%0,%1,%2,%3};"
        : "+f"(c[0]), "+f"(c[1]), "+f"(c[2]), "+f"(c[3])
        : "r"(a[0]), "r"(a[1]), "r"(a[2]), "r"(a[3]), "r"(b0), "r"(b1));
}

// f32x2 helpers (attention path)
__device__ __forceinline__ ull pack2(float a, float b) {
    ull r; asm("mov.b64 %0, {%1, %2};" : "=l"(r) : "f"(a), "f"(b)); return r;
}
__device__ __forceinline__ void unpack2(ull v, float& a, float& b) {
    asm("mov.b64 {%0, %1}, %2;" : "=f"(a), "=f"(b) : "l"(v));
}
__device__ __forceinline__ void fma2(ull& d, ull a, ull b) {
    asm("fma.rn.f32x2 %0, %1, %2, %0;" : "+l"(d) : "l"(a), "l"(b));
}

// ===========================================================================
// Weight prep: fp32 -> fp16
// ===========================================================================
__global__ void prep_kernel(const float* __restrict__ ff1w, const float* __restrict__ ff2w)
{
    int i = blockIdx.x * blockDim.x + threadIdx.x;
    if (i >= 131072) return;
    g_w1h[i] = __float2half(ff1w[i]);
    g_w2h[i] = __float2half(ff2w[i]);
}

// ===========================================================================
// K/V projection (gate != 0 path only)
// ===========================================================================
__global__ void kv_kernel(const float* __restrict__ tokens,
                          const float* __restrict__ kw,
                          const float* __restrict__ vw,
                          const float* __restrict__ gate)
{
    if (gate[0] == 0.0f) return;
    __shared__ float tok[512];
    const int bn = blockIdx.x;
    const int b = bn >> 8, n = bn & 255;
    const float* tr = tokens + (size_t)(b * 256 + n) * 512;
    for (int i = threadIdx.x; i < 512; i += 128) tok[i] = tr[i];
    __syncthreads();
    const int t = threadIdx.x;
    const float* kr = kw + (size_t)t * 512;
    const float* vr = vw + (size_t)t * 512;
    float sk = 0.f, sv = 0.f;
    #pragma unroll 8
    for (int c = 0; c < 512; c++) {
        float x = tok[c];
        sk = fmaf(kr[c], x, sk);
        sv = fmaf(vr[c], x, sv);
    }
    const int h = t >> 5, d = t & 31;
    const size_t base = ((size_t)(b * NHEADS + h) * DH + d) * NTOK + n;
    g_kt[base] = sk;
    g_vt[base] = sv;
}

// ---------------------------------------------------------------------------
// scalar block GEMM (attention path only)
// ---------------------------------------------------------------------------
template<int COUT, int CIN>
__device__ __forceinline__ void gemm_block(const float* __restrict__ Wg,
                                           const float* __restrict__ Xsh,
                                           ull* __restrict__ W2,
                                           ull acc2[][4])
{
    constexpr int NP  = COUT / 64;
    constexpr int KC  = 16;
    constexpr int KCp = KC + 1;
    constexpr int KF4 = KC / 4;

    const int tid = threadIdx.x;
    const int r0  = tid >> 3;
    const int c0  = (tid & 7) * 4;
    const bool active = tid < COUT / 2;
    const int rr = tid & 31;
    const int pp = tid >> 5;

    const float* rowA = Wg + (size_t)(rr + 64 * pp) * CIN;
    const float* rowB = rowA + (size_t)32 * CIN;

    float4 wva[KF4], wvb[KF4];
    if (active) {
        #pragma unroll
        for (int f = 0; f < KF4; f++) {
            wva[f] = *(const float4*)(rowA + 4 * f);
            wvb[f] = *(const float4*)(rowB + 4 * f);
        }
    }
    for (int k0 = 0; k0 < CIN; k0 += KC) {
        __syncthreads();
        if (active) {
            ull* dst = W2 + (pp * 32 + rr) * KCp;
            #pragma unroll
            for (int f = 0; f < KF4; f++) {
                dst[4 * f + 0] = pack2(wva[f].x, wvb[f].x);
                dst[4 * f + 1] = pack2(wva[f].y, wvb[f].y);
                dst[4 * f + 2] = pack2(wva[f].z, wvb[f].z);
                dst[4 * f + 3] = pack2(wva[f].w, wvb[f].w);
            }
        }
        __syncthreads();
        const int kn = k0 + KC;
        if (active && kn < CIN) {
            #pragma unroll
            for (int f = 0; f < KF4; f++) {
                wva[f] = *(const float4*)(rowA + kn + 4 * f);
                wvb[f] = *(const float4*)(rowB + kn + 4 * f);
            }
        }
        #pragma unroll
        for (int kk = 0; kk < KC; kk++) {
            float4 x4 = *(const float4*)(Xsh + (k0 + kk) * ST + c0);
            ull xd0 = pack2(x4.x, x4.x);
            ull xd1 = pack2(x4.y, x4.y);
            ull xd2 = pack2(x4.z, x4.z);
            ull xd3 = pack2(x4.w, x4.w);
            #pragma unroll
            for (int p = 0; p < NP; p++) {
                ull w = W2[(p * 32 + r0) * KCp + kk];
                fma2(acc2[p][0], w, xd0);
                fma2(acc2[p][1], w, xd1);
                fma2(acc2[p][2], w, xd2);
                fma2(acc2[p][3], w, xd3);
            }
        }
    }
}

// ===========================================================================
// Attention path (gate != 0): writes feat + tanh(g)*proj(attn) into g_f.
// ===========================================================================
__global__ void __launch_bounds__(256, 1)
attn_kernel(const float* __restrict__ feat,
            const float* __restrict__ qw,    const float* __restrict__ qb,
            const float* __restrict__ projw, const float* __restrict__ projb,
            const float* __restrict__ gate)
{
    if (gate[0] == 0.0f) return;
    extern __shared__ float sm[];
    float* F  = sm;            // [256][32]
    float* Q  = sm + 8192;     // [128][32]
    float* KV = sm + 12288;    // [32][256]
    float* AO = sm + 20480;    // [128][32]
    float* SC = sm + 24576;    // [32][256]
    ull*   W2 = (ull*)(sm + 24576);

    const int b   = blockIdx.y;
    const int s0  = blockIdx.x * ST;
    const int tid = threadIdx.x;
    const int r0  = tid >> 3;
    const int c0  = (tid & 7) * 4;
    const float tg = tanhf(gate[0]);

    const float* fb = feat + (size_t)b * QCH * STOT + s0;
    for (int i = tid; i < QCH * ST / 4; i += 256) {
        int c = i >> 3, s4 = (i & 7) * 4;
        *(float4*)(F + c * ST + s4) = *(const float4*)(fb + (size_t)c * STOT + s4);
    }
    __syncthreads();

    {   // Q = qw @ F + qb
        ull acc2[2][4] = {};
        gemm_block<128, 256>(qw, F, W2, acc2);
        #pragma unroll
        for (int p = 0; p < 2; p++) {
            int ra = r0 + 64 * p, rb = ra + 32;
            float ba = qb[ra], bb = qb[rb];
            #pragma unroll
            for (int j = 0; j < 4; j++) {
                float lo, hi; unpack2(acc2[p][j], lo, hi);
                Q[ra * ST + c0 + j] = lo + ba;
                Q[rb * ST + c0 + j] = hi + bb;
            }
        }
    }
    __syncthreads();

    for (int h = 0; h < NHEADS; h++) {
        const float* kp = g_kt + (size_t)(b * NHEADS + h) * DH * NTOK;
        for (int i = tid; i < DH * NTOK / 4; i += 256)
            *(float4*)(KV + i * 4) = *(const float4*)(kp + i * 4);
        __syncthreads();
        {
            const int st0 = (tid >> 5) * 4;
            const int n0  = (tid & 31) * 8;
            float acc[4][8];
            #pragma unroll
            for (int i = 0; i < 4; i++)
                #pragma unroll
                for (int j = 0; j < 8; j++) acc[i][j] = 0.f;
            #pragma unroll 4
            for (int d = 0; d < DH; d++) {
                float4 qv = *(const float4*)(Q + (h * DH + d) * ST + st0);
                float4 ka = *(const float4*)(KV + d * NTOK + n0);
                float4 kb = *(const float4*)(KV + d * NTOK + n0 + 4);
                float qr[4] = {qv.x, qv.y, qv.z, qv.w};
                float kr[8] = {ka.x, ka.y, ka.z, ka.w, kb.x, kb.y, kb.z, kb.w};
                #pragma unroll
                for (int i = 0; i < 4; i++)
                    #pragma unroll
                    for (int j = 0; j < 8; j++)
                        acc[i][j] = fmaf(qr[i], kr[j], acc[i][j]);
            }
            const float scale = 0.17677669529663687f;
            #pragma unroll
            for (int i = 0; i < 4; i++)
                #pragma unroll
                for (int j = 0; j < 8; j++)
                    SC[(st0 + i) * NTOK + n0 + j] = acc[i][j] * scale;
        }
        __syncthreads();
        {
            const int wid = tid >> 5, lane = tid & 31;
            #pragma unroll
            for (int rrr = 0; rrr < 4; rrr++) {
                int row = wid * 4 + rrr;
                float v[8], m = -1e30f;
                #pragma unroll
                for (int k = 0; k < 8; k++) {
                    v[k] = SC[row * NTOK + lane + 32 * k];
                    m = fmaxf(m, v[k]);
                }
                #pragma unroll
                for (int o = 16; o; o >>= 1) m = fmaxf(m, __shfl_xor_sync(0xffffffffu, m, o));
                float s = 0.f;
                #pragma unroll
                for (int k = 0; k < 8; k++) { v[k] = __expf(v[k] - m); s += v[k]; }
                #pragma unroll
                for (int o = 16; o; o >>= 1) s += __shfl_xor_sync(0xffffffffu, s, o);
                float inv = 1.0f / s;
                #pragma unroll
                for (int k = 0; k < 8; k++) SC[row * NTOK + lane + 32 * k] = v[k] * inv;
            }
        }
        __syncthreads();
        const float* vp = g_vt + (size_t)(b * NHEADS + h) * DH * NTOK;
        for (int i = tid; i < DH * NTOK / 4; i += 256)
            *(float4*)(KV + i * 4) = *(const float4*)(vp + i * 4);
        __syncthreads();
        {
            const int st = tid >> 3, nl = tid & 7;
            float part[DH];
            #pragma unroll
            for (int d = 0; d < DH; d++) part[d] = 0.f;
            #pragma unroll 4
            for (int k = 0; k < 32; k++) {
                int n = nl + 8 * k;
                float pv = SC[st * NTOK + n];
                #pragma unroll
                for (int d = 0; d < DH; d++)
                    part[d] = fmaf(pv, KV[d * NTOK + n], part[d]);
            }
            #pragma unroll
            for (int d = 0; d < DH; d++) {
                part[d] += __shfl_xor_sync(0xffffffffu, part[d], 1);
                part[d] += __shfl_xor_sync(0xffffffffu, part[d], 2);
                part[d] += __shfl_xor_sync(0xffffffffu, part[d], 4);
            }
            #pragma unroll
            for (int m2 = 0; m2 < 4; m2++) {
                int d = nl * 4 + m2;
                AO[(h * DH + d) * ST + st] = part[d];
            }
        }
        __syncthreads();
    }

    {   // proj + gated residual -> g_f
        ull acc2[4][4] = {};
        gemm_block<256, 128>(projw, AO, W2, acc2);
        float* gf = g_f + (size_t)b * QCH * STOT + s0;
        #pragma unroll
        for (int p = 0; p < 4; p++) {
            int ra = r0 + 64 * p, rb = ra + 32;
            float ba = projb[ra], bb = projb[rb];
            #pragma unroll
            for (int j = 0; j < 4; j++) {
                float lo, hi; unpack2(acc2[p][j], lo, hi);
                gf[(size_t)ra * STOT + c0 + j] = F[ra * ST + c0 + j] + tg * (lo + ba);
                gf[(size_t)rb * STOT + c0 + j] = F[rb * ST + c0 + j] + tg * (hi + bb);
            }
        }
    }
}

// ===========================================================================
// FF kernel via mma.sync fp16, 3 CTAs/SM, M-tile 32, warp tile 32x32
// (1M x 8N over 256-n units), k16-granular 8KB W slots, static unrolling,
// single __syncthreads per unit.  0.5 ldsm per MMA.
// out = src + FF2(silu(FF1(src)+b1)) + b2
// SMEM (64KB/CTA -> 3 resident CTAs):
//   X[32][256] fp16 @0 (16KB), H[32][512] fp16 @16384 (32KB),
//   W double buffers @49152 (2 x 8KB = 256 rows x 32B each).
// Units (64): FF1: nch in {0,1} (256 n) x kh 0..15 (16 k)
//             FF2: ko 0..31 (16 k, 256 n)
// X/H swizzle: 16B atom index ^= (row & 7).
// W-slot swizzle (32B rows, 2 atoms): atom ^= (row>>2) & 1
//   -> 8 rows of each ldsm matrix land on 8 distinct 16B bank groups.
// ===========================================================================
#define SM_H  16384u
#define SM_W  49152u
#define SMEM_FF 65536

__global__ void __launch_bounds__(256, 3)
ff_mma_kernel(const float* __restrict__ feat,
              const float* __restrict__ ff1b, const float* __restrict__ ff2b,
              const float* __restrict__ gate, float* __restrict__ out)
{
    extern __shared__ char smc[];
    const uint32_t sb = smem_u32(smc);
    const int tid  = threadIdx.x;
    const int wid  = tid >> 5, lane = tid & 31;
    const int g    = lane >> 2, tg = lane & 3;
    const int q    = lane >> 3, r8 = lane & 7;
    const int b    = blockIdx.y;
    const int s0   = blockIdx.x * 32;

    const float* src  = (gate[0] == 0.0f) ? feat : (const float*)g_f;
    const float* srcb = src + (size_t)b * QCH * STOT + s0;
    float*       outb = out + (size_t)b * QCH * STOT + s0;

    // ---- staging geometry: thread stages W row `tid`, both 16B atoms ----
    const uint32_t swbit = (uint32_t)((tid >> 2) & 1) << 4;
    const uint32_t dstOff0 = sb + SM_W + (uint32_t)tid * 32u + swbit;
    const uint32_t dstOff1 = sb + SM_W + (uint32_t)tid * 32u + (swbit ^ 16u);
    const char* w1src = (const char*)g_w1h + (uint32_t)tid * 512u;   // +nch*131072 +kh*32 (+16)
    const char* w2src = (const char*)g_w2h + (uint32_t)tid * 1024u;  // +ko*32 (+16)

    // ---- preload weight unit 0 (FF1 nch0 kh0) ----
    cp16(dstOff0, w1src);
    cp16(dstOff1, w1src + 16);
    asm volatile("cp.async.commit_group;");

    // ---- X convert: src[c][s0+m] -> X[m][k=c] fp16, swizzled ----
    {
        const int c = tid;
        const float* row = srcb + (size_t)c * STOT;
        const uint32_t katom  = (uint32_t)c >> 3;
        const uint32_t inatom = ((uint32_t)c * 2) & 15;
        #pragma unroll
        for (int s4 = 0; s4 < 32; s4 += 4) {
            float4 v = *(const float4*)(row + s4);
            float vv[4] = {v.x, v.y, v.z, v.w};
            #pragma unroll
            for (int e = 0; e < 4; e++) {
                int m = s4 + e;
                uint32_t off = (uint32_t)m * 512u + ((katom ^ (uint32_t)(m & 7)) << 4) + inatom;
                *(__half*)(smc + off) = __float2half(vv[e]);
            }
        }
    }

    // ---- ldsm geometry ----
    const int aRow  = (q & 1) * 8 + r8;            // rows 0..15; fC at +16
    const int aQk   = q >> 1;
    const uint32_t r7A   = (uint32_t)(aRow & 7);
    const uint32_t aBit0 = ((uint32_t)aQk ^ (r7A & 1)) << 4;
    const uint32_t r7hi  = r7A >> 1;               // 2 bits, XORed with k index
    // A bases (k term added per unit: ((k ^ r7hi) << 5))
    const uint32_t aBX = sb + (uint32_t)aRow * 512u + aBit0;
    const uint32_t aBH = sb + SM_H + (uint32_t)aRow * 1024u + aBit0;
    // B: rows wid*32 + (q>>1)*8 + r8 (ldsm0: n0..15) and +16 (ldsm1)
    const int bRow = wid * 32 + (q >> 1) * 8 + r8;
    const uint32_t bA0 = sb + SM_W + (uint32_t)bRow * 32u
                       + (((uint32_t)(q & 1) ^ ((uint32_t)(bRow >> 2) & 1)) << 4);
    // second matrix at row+16: (row>>2)&1 unchanged -> just +512 bytes

    float acc[2][4][4];

    // =================== FF1 phase (2 nch x 16 kh units) ==================
    #pragma unroll 1
    for (int nch = 0; nch < 2; nch++) {
        #pragma unroll
        for (int mt = 0; mt < 2; mt++)
            #pragma unroll
            for (int nt = 0; nt < 4; nt++)
                #pragma unroll
                for (int j = 0; j < 4; j++) acc[mt][nt][j] = 0.f;

        const char* wnb = w1src + nch * 131072;

        #pragma unroll
        for (int kh = 0; kh < 16; kh++) {
            asm volatile("cp.async.wait_group 0;" ::: "memory");
            __syncthreads();   // publish slot kh&1; separate stage/compute

            if (kh < 15) {
                const uint32_t db = (uint32_t)(((kh + 1) & 1) * 8192);
                cp16(dstOff0 + db, wnb + (kh + 1) * 32);
                cp16(dstOff1 + db, wnb + (kh + 1) * 32 + 16);
            } else if (nch == 0) {
                cp16(dstOff0, wnb + 131072);
                cp16(dstOff1, wnb + 131072 + 16);
            } else {
                cp16(dstOff0, w2src);
                cp16(dstOff1, w2src + 16);
            }
            asm volatile("cp.async.commit_group;");

            const uint32_t slotOff = (uint32_t)((kh & 1) * 8192);
            const uint32_t aA = aBX + (((uint32_t)kh ^ r7hi) << 5);
            const uint32_t bAdr = bA0 + slotOff;

            uint32_t fA[4], fC[4], fB0[4], fB1[4];
            ldsm4(fA[0], fA[1], fA[2], fA[3], aA);
            ldsm4(fC[0], fC[1], fC[2], fC[3], aA + 8192u);
            ldsm4(fB0[0], fB0[1], fB0[2], fB0[3], bAdr);
            ldsm4(fB1[0], fB1[1], fB1[2], fB1[3], bAdr + 512u);
            mma16816(acc[0][0], fA, fB0[0], fB0[1]);
            mma16816(acc[0][1], fA, fB0[2], fB0[3]);
            mma16816(acc[0][2], fA, fB1[0], fB1[1]);
            mma16816(acc[0][3], fA, fB1[2], fB1[3]);
            mma16816(acc[1][0], fC, fB0[0], fB0[1]);
            mma16816(acc[1][1], fC, fB0[2], fB0[3]);
            mma16816(acc[1][2], fC, fB1[0], fB1[1]);
            mma16816(acc[1][3], fC, fB1[2], fB1[3]);
        }

        // epilogue: bias + silu -> H fp16 (swizzled, 64 atoms/row)
        #pragma unroll
        for (int nt = 0; nt < 4; nt++) {
            int cg = nch * 256 + wid * 32 + nt * 8 + tg * 2;
            float b1v = __ldg(ff1b + cg);
            float b2v = __ldg(ff1b + cg + 1);
            uint32_t katom = (uint32_t)(cg >> 3);
            uint32_t inb   = ((uint32_t)cg * 2) & 15;
            #pragma unroll
            for (int mt = 0; mt < 2; mt++) {
                int m0 = mt * 16 + g;
                float x0 = acc[mt][nt][0] + b1v;
                float x1 = acc[mt][nt][1] + b2v;
                float x2 = acc[mt][nt][2] + b1v;
                float x3 = acc[mt][nt][3] + b2v;
                float h0 = x0 / (1.0f + __expf(-x0));
                float h1 = x1 / (1.0f + __expf(-x1));
                float h2 = x2 / (1.0f + __expf(-x2));
                float h3 = x3 / (1.0f + __expf(-x3));
                uint32_t off0 = SM_H + (uint32_t)m0 * 1024u + ((katom ^ (uint32_t)(m0 & 7)) << 4) + inb;
                uint32_t off1 = SM_H + (uint32_t)(m0 + 8) * 1024u + ((katom ^ (uint32_t)((m0 + 8) & 7)) << 4) + inb;
                *(__half2*)(smc + off0) = __floats2half2_rn(h0, h1);
                *(__half2*)(smc + off1) = __floats2half2_rn(h2, h3);
            }
        }
    }

    // =================== FF2 phase (32 ko units, acc persists) ============
    #pragma unroll
    for (int mt = 0; mt < 2; mt++)
        #pragma unroll
        for (int nt = 0; nt < 4; nt++)
            #pragma unroll
            for (int j = 0; j < 4; j++) acc[mt][nt][j] = 0.f;

    #pragma unroll
    for (int ko = 0; ko < 32; ko++) {
        asm volatile("cp.async.wait_group 0;" ::: "memory");
        __syncthreads();

        if (ko < 31) {
            const uint32_t db = (uint32_t)(((ko + 1) & 1) * 8192);
            cp16(dstOff0 + db, w2src + (ko + 1) * 32);
            cp16(dstOff1 + db, w2src + (ko + 1) * 32 + 16);
            asm volatile("cp.async.commit_group;");
        }

        const uint32_t slotOff = (uint32_t)((ko & 1) * 8192);
        const uint32_t aA = aBH + (((uint32_t)ko ^ r7hi) << 5);
        const uint32_t bAdr = bA0 + slotOff;

        uint32_t fA[4], fC[4], fB0[4], fB1[4];
        ldsm4(fA[0], fA[1], fA[2], fA[3], aA);
        ldsm4(fC[0], fC[1], fC[2], fC[3], aA + 16384u);
        ldsm4(fB0[0], fB0[1], fB0[2], fB0[3], bAdr);
        ldsm4(fB1[0], fB1[1], fB1[2], fB1[3], bAdr + 512u);
        mma16816(acc[0][0], fA, fB0[0], fB0[1]);
        mma16816(acc[0][1], fA, fB0[2], fB0[3]);
        mma16816(acc[0][2], fA, fB1[0], fB1[1]);
        mma16816(acc[0][3], fA, fB1[2], fB1[3]);
        mma16816(acc[1][0], fC, fB0[0], fB0[1]);
        mma16816(acc[1][1], fC, fB0[2], fB0[3]);
        mma16816(acc[1][2], fC, fB1[0], fB1[1]);
        mma16816(acc[1][3], fC, fB1[2], fB1[3]);
    }

    // FF2 epilogue: D = 32m x 256c; four 64-channel passes via Xf [64c][36m]
    {
        float* Xf = (float*)smc;
        #pragma unroll
        for (int p = 0; p < 4; p++) {
            __syncthreads();
            if ((wid >> 1) == p) {
                #pragma unroll
                for (int nt = 0; nt < 4; nt++) {
                    int cc = (wid & 1) * 32 + nt * 8 + tg * 2;
                    #pragma unroll
                    for (int mt = 0; mt < 2; mt++) {
                        int m0 = mt * 16 + g;
                        Xf[cc * 36 + m0]           = acc[mt][nt][0];
                        Xf[(cc + 1) * 36 + m0]     = acc[mt][nt][1];
                        Xf[cc * 36 + m0 + 8]       = acc[mt][nt][2];
                        Xf[(cc + 1) * 36 + m0 + 8] = acc[mt][nt][3];
                    }
                }
            }
            __syncthreads();
            {
                int cc = tid >> 2, ms = (tid & 3) * 8;
                int cg = p * 64 + cc;
                float bias = __ldg(ff2b + cg);
                const float* sr = srcb + (size_t)cg * STOT + ms;
                float* ob = outb + (size_t)cg * STOT + ms;
                #pragma unroll
                for (int j = 0; j < 2; j++) {
                    float4 rv = *(const float4*)(sr + 4 * j);
                    float4 o;
                    o.x = Xf[cc * 36 + ms + 4 * j + 0] + bias + rv.x;
                    o.y = Xf[cc * 36 + ms + 4 * j + 1] + bias + rv.y;
                    o.z = Xf[cc * 36 + ms + 4 * j + 2] + bias + rv.z;
                    o.w = Xf[cc * 36 + ms + 4 * j + 3] + bias + rv.w;
                    *(float4*)(ob + 4 * j) = o;
                }
            }
        }
    }
}

extern "C" void kernel_launch(void* const* d_in, const int* in_sizes, int n_in,
                              void* d_out, int out_size)
{
    const float* feat   = (const float*)d_in[0];
    const float* tokens = (const float*)d_in[1];
    const float* qw     = (const float*)d_in[2];
    const float* qb     = (const float*)d_in[3];
    const float* kw     = (const float*)d_in[4];
    const float* vw     = (const float*)d_in[5];
    const float* projw  = (const float*)d_in[6];
    const float* projb  = (const float*)d_in[7];
    const float* ff1w   = (const float*)d_in[8];
    const float* ff1b   = (const float*)d_in[9];
    const float* ff2w   = (const float*)d_in[10];
    const float* ff2b   = (const float*)d_in[11];
    const float* gate   = (const float*)d_in[12];
    float* out = (float*)d_out;

    cudaFuncSetAttribute(attn_kernel, cudaFuncAttributeMaxDynamicSharedMemorySize, 131072);
    cudaFuncSetAttribute(ff_mma_kernel, cudaFuncAttributeMaxDynamicSharedMemorySize, SMEM_FF);

    prep_kernel<<<512, 256>>>(ff1w, ff2w);
    kv_kernel<<<NB * NTOK, 128>>>(tokens, kw, vw, gate);
    attn_kernel<<<dim3(STOT / ST, NB), 256, 131072>>>(feat, qw, qb, projw, projb, gate);
    ff_mma_kernel<<<dim3(STOT / 32, NB), 256, SMEM_FF>>>(feat, ff1b, ff2b, gate, out);
}

// round 17
// speedup vs baseline: 1.9296x; 1.9296x over previous
#include <cuda_runtime.h>
#include <cuda_fp16.h>
#include <cstdint>

typedef unsigned long long ull;

#define NB     4
#define NHEADS 4
#define DH     32
#define NTOK   256
#define QCH    256
#define STOT   16384
#define ST     32

// ---------------- device global scratch ----------------
__device__ __align__(16) float g_kt[NB * NHEADS * DH * NTOK];
__device__ __align__(16) float g_vt[NB * NHEADS * DH * NTOK];
__device__ __align__(16) float g_f[(size_t)NB * QCH * STOT];   // gate!=0 path
// unit-contiguous, pre-swizzled weight tiles (32 units FF1, 32 units FF2)
__device__ __align__(16) __half g_w1h[512 * 256];
__device__ __align__(16) __half g_w2h[256 * 512];

// ---------------- helpers ----------------
__device__ __forceinline__ uint32_t smem_u32(const void* p) {
    uint32_t a;
    asm("{ .reg .u64 t; cvta.to.shared.u64 t, %1; cvt.u32.u64 %0, t; }" : "=r"(a) : "l"(p));
    return a;
}
__device__ __forceinline__ void cp16(uint32_t s, const void* g) {
    asm volatile("cp.async.cg.shared.global [%0], [%1], 16;" :: "r"(s), "l"(g));
}
__device__ __forceinline__ void ldsm4(uint32_t& r0, uint32_t& r1, uint32_t& r2, uint32_t& r3, uint32_t a) {
    asm volatile("ldmatrix.sync.aligned.m8n8.x4.shared.b16 {%0,%1,%2,%3}, [%4];"
        : "=r"(r0), "=r"(r1), "=r"(r2), "=r"(r3) : "r"(a));
}
__device__ __forceinline__ void mma16816(float* c, const uint32_t* a, uint32_t b0, uint32_t b1) {
    asm volatile("mma.sync.aligned.m16n8k16.row.col.f32.f16.f16.f32 "
        "{%0,%1,%2,%3}, {%4,%5,%6,%7}, {%8,%9}, {%0,%1,%2,%3};"
        : "+f"(c[0]), "+f"(c[1]), "+f"(c[2]), "+f"(c[3])
        : "r"(a[0]), "r"(a[1]), "r"(a[2]), "r"(a[3]), "r"(b0), "r"(b1));
}

// f32x2 helpers (attention path)
__device__ __forceinline__ ull pack2(float a, float b) {
    ull r; asm("mov.b64 %0, {%1, %2};" : "=l"(r) : "f"(a), "f"(b)); return r;
}
__device__ __forceinline__ void unpack2(ull v, float& a, float& b) {
    asm("mov.b64 {%0, %1}, %2;" : "=f"(a), "=f"(b) : "l"(v));
}
__device__ __forceinline__ void fma2(ull& d, ull a, ull b) {
    asm("fma.rn.f32x2 %0, %1, %2, %0;" : "+l"(d) : "l"(a), "l"(b));
}

// ===========================================================================
// Weight prep: fp32 -> fp16, re-laid out unit-contiguous + pre-swizzled.
// FF1 unit = nch*16+kh (nch<2, kh<16): 8KB = [256 n][32B kslice]
// FF2 unit = ko (ko<32):               8KB = [256 n][32B kslice]
// swizzle within 32B row (2 atoms): atom ^= (n>>2)&1
// ===========================================================================
__global__ void prep_kernel(const float* __restrict__ ff1w, const float* __restrict__ ff2w)
{
    int i = blockIdx.x * blockDim.x + threadIdx.x;
    if (i >= 131072) return;
    {
        int r = i >> 8, c = i & 255;            // FF1 [512 n][256 k]
        int nch = r >> 8, nl = r & 255, kh = c >> 4, kl = c & 15;
        uint32_t off = (uint32_t)(nch * 16 + kh) * 8192u
                     + (uint32_t)nl * 32u
                     + (uint32_t)(((kl >> 3) ^ ((nl >> 2) & 1)) << 4)
                     + (uint32_t)(kl & 7) * 2u;
        *(__half*)((char*)g_w1h + off) = __float2half(ff1w[i]);
    }
    {
        int r = i >> 9, c = i & 511;            // FF2 [256 n][512 k]
        int ko = c >> 4, kl = c & 15;
        uint32_t off = (uint32_t)ko * 8192u
                     + (uint32_t)r * 32u
                     + (uint32_t)(((kl >> 3) ^ ((r >> 2) & 1)) << 4)
                     + (uint32_t)(kl & 7) * 2u;
        *(__half*)((char*)g_w2h + off) = __float2half(ff2w[i]);
    }
}

// ===========================================================================
// K/V projection (gate != 0 path only)
// ===========================================================================
__global__ void kv_kernel(const float* __restrict__ tokens,
                          const float* __restrict__ kw,
                          const float* __restrict__ vw,
                          const float* __restrict__ gate)
{
    if (gate[0] == 0.0f) return;
    __shared__ float tok[512];
    const int bn = blockIdx.x;
    const int b = bn >> 8, n = bn & 255;
    const float* tr = tokens + (size_t)(b * 256 + n) * 512;
    for (int i = threadIdx.x; i < 512; i += 128) tok[i] = tr[i];
    __syncthreads();
    const int t = threadIdx.x;
    const float* kr = kw + (size_t)t * 512;
    const float* vr = vw + (size_t)t * 512;
    float sk = 0.f, sv = 0.f;
    #pragma unroll 8
    for (int c = 0; c < 512; c++) {
        float x = tok[c];
        sk = fmaf(kr[c], x, sk);
        sv = fmaf(vr[c], x, sv);
    }
    const int h = t >> 5, d = t & 31;
    const size_t base = ((size_t)(b * NHEADS + h) * DH + d) * NTOK + n;
    g_kt[base] = sk;
    g_vt[base] = sv;
}

// ---------------------------------------------------------------------------
// scalar block GEMM (attention path only)
// ---------------------------------------------------------------------------
template<int COUT, int CIN>
__device__ __forceinline__ void gemm_block(const float* __restrict__ Wg,
                                           const float* __restrict__ Xsh,
                                           ull* __restrict__ W2,
                                           ull acc2[][4])
{
    constexpr int NP  = COUT / 64;
    constexpr int KC  = 16;
    constexpr int KCp = KC + 1;
    constexpr int KF4 = KC / 4;

    const int tid = threadIdx.x;
    const int r0  = tid >> 3;
    const int c0  = (tid & 7) * 4;
    const bool active = tid < COUT / 2;
    const int rr = tid & 31;
    const int pp = tid >> 5;

    const float* rowA = Wg + (size_t)(rr + 64 * pp) * CIN;
    const float* rowB = rowA + (size_t)32 * CIN;

    float4 wva[KF4], wvb[KF4];
    if (active) {
        #pragma unroll
        for (int f = 0; f < KF4; f++) {
            wva[f] = *(const float4*)(rowA + 4 * f);
            wvb[f] = *(const float4*)(rowB + 4 * f);
        }
    }
    for (int k0 = 0; k0 < CIN; k0 += KC) {
        __syncthreads();
        if (active) {
            ull* dst = W2 + (pp * 32 + rr) * KCp;
            #pragma unroll
            for (int f = 0; f < KF4; f++) {
                dst[4 * f + 0] = pack2(wva[f].x, wvb[f].x);
                dst[4 * f + 1] = pack2(wva[f].y, wvb[f].y);
                dst[4 * f + 2] = pack2(wva[f].z, wvb[f].z);
                dst[4 * f + 3] = pack2(wva[f].w, wvb[f].w);
            }
        }
        __syncthreads();
        const int kn = k0 + KC;
        if (active && kn < CIN) {
            #pragma unroll
            for (int f = 0; f < KF4; f++) {
                wva[f] = *(const float4*)(rowA + kn + 4 * f);
                wvb[f] = *(const float4*)(rowB + kn + 4 * f);
            }
        }
        #pragma unroll
        for (int kk = 0; kk < KC; kk++) {
            float4 x4 = *(const float4*)(Xsh + (k0 + kk) * ST + c0);
            ull xd0 = pack2(x4.x, x4.x);
            ull xd1 = pack2(x4.y, x4.y);
            ull xd2 = pack2(x4.z, x4.z);
            ull xd3 = pack2(x4.w, x4.w);
            #pragma unroll
            for (int p = 0; p < NP; p++) {
                ull w = W2[(p * 32 + r0) * KCp + kk];
                fma2(acc2[p][0], w, xd0);
                fma2(acc2[p][1], w, xd1);
                fma2(acc2[p][2], w, xd2);
                fma2(acc2[p][3], w, xd3);
            }
        }
    }
}

// ===========================================================================
// Attention path (gate != 0): writes feat + tanh(g)*proj(attn) into g_f.
// ===========================================================================
__global__ void __launch_bounds__(256, 1)
attn_kernel(const float* __restrict__ feat,
            const float* __restrict__ qw,    const float* __restrict__ qb,
            const float* __restrict__ projw, const float* __restrict__ projb,
            const float* __restrict__ gate)
{
    if (gate[0] == 0.0f) return;
    extern __shared__ float sm[];
    float* F  = sm;            // [256][32]
    float* Q  = sm + 8192;     // [128][32]
    float* KV = sm + 12288;    // [32][256]
    float* AO = sm + 20480;    // [128][32]
    float* SC = sm + 24576;    // [32][256]
    ull*   W2 = (ull*)(sm + 24576);

    const int b   = blockIdx.y;
    const int s0  = blockIdx.x * ST;
    const int tid = threadIdx.x;
    const int r0  = tid >> 3;
    const int c0  = (tid & 7) * 4;
    const float tg = tanhf(gate[0]);

    const float* fb = feat + (size_t)b * QCH * STOT + s0;
    for (int i = tid; i < QCH * ST / 4; i += 256) {
        int c = i >> 3, s4 = (i & 7) * 4;
        *(float4*)(F + c * ST + s4) = *(const float4*)(fb + (size_t)c * STOT + s4);
    }
    __syncthreads();

    {   // Q = qw @ F + qb
        ull acc2[2][4] = {};
        gemm_block<128, 256>(qw, F, W2, acc2);
        #pragma unroll
        for (int p = 0; p < 2; p++) {
            int ra = r0 + 64 * p, rb = ra + 32;
            float ba = qb[ra], bb = qb[rb];
            #pragma unroll
            for (int j = 0; j < 4; j++) {
                float lo, hi; unpack2(acc2[p][j], lo, hi);
                Q[ra * ST + c0 + j] = lo + ba;
                Q[rb * ST + c0 + j] = hi + bb;
            }
        }
    }
    __syncthreads();

    for (int h = 0; h < NHEADS; h++) {
        const float* kp = g_kt + (size_t)(b * NHEADS + h) * DH * NTOK;
        for (int i = tid; i < DH * NTOK / 4; i += 256)
            *(float4*)(KV + i * 4) = *(const float4*)(kp + i * 4);
        __syncthreads();
        {
            const int st0 = (tid >> 5) * 4;
            const int n0  = (tid & 31) * 8;
            float acc[4][8];
            #pragma unroll
            for (int i = 0; i < 4; i++)
                #pragma unroll
                for (int j = 0; j < 8; j++) acc[i][j] = 0.f;
            #pragma unroll 4
            for (int d = 0; d < DH; d++) {
                float4 qv = *(const float4*)(Q + (h * DH + d) * ST + st0);
                float4 ka = *(const float4*)(KV + d * NTOK + n0);
                float4 kb = *(const float4*)(KV + d * NTOK + n0 + 4);
                float qr[4] = {qv.x, qv.y, qv.z, qv.w};
                float kr[8] = {ka.x, ka.y, ka.z, ka.w, kb.x, kb.y, kb.z, kb.w};
                #pragma unroll
                for (int i = 0; i < 4; i++)
                    #pragma unroll
                    for (int j = 0; j < 8; j++)
                        acc[i][j] = fmaf(qr[i], kr[j], acc[i][j]);
            }
            const float scale = 0.17677669529663687f;
            #pragma unroll
            for (int i = 0; i < 4; i++)
                #pragma unroll
                for (int j = 0; j < 8; j++)
                    SC[(st0 + i) * NTOK + n0 + j] = acc[i][j] * scale;
        }
        __syncthreads();
        {
            const int wid = tid >> 5, lane = tid & 31;
            #pragma unroll
            for (int rrr = 0; rrr < 4; rrr++) {
                int row = wid * 4 + rrr;
                float v[8], m = -1e30f;
                #pragma unroll
                for (int k = 0; k < 8; k++) {
                    v[k] = SC[row * NTOK + lane + 32 * k];
                    m = fmaxf(m, v[k]);
                }
                #pragma unroll
                for (int o = 16; o; o >>= 1) m = fmaxf(m, __shfl_xor_sync(0xffffffffu, m, o));
                float s = 0.f;
                #pragma unroll
                for (int k = 0; k < 8; k++) { v[k] = __expf(v[k] - m); s += v[k]; }
                #pragma unroll
                for (int o = 16; o; o >>= 1) s += __shfl_xor_sync(0xffffffffu, s, o);
                float inv = 1.0f / s;
                #pragma unroll
                for (int k = 0; k < 8; k++) SC[row * NTOK + lane + 32 * k] = v[k] * inv;
            }
        }
        __syncthreads();
        const float* vp = g_vt + (size_t)(b * NHEADS + h) * DH * NTOK;
        for (int i = tid; i < DH * NTOK / 4; i += 256)
            *(float4*)(KV + i * 4) = *(const float4*)(vp + i * 4);
        __syncthreads();
        {
            const int st = tid >> 3, nl = tid & 7;
            float part[DH];
            #pragma unroll
            for (int d = 0; d < DH; d++) part[d] = 0.f;
            #pragma unroll 4
            for (int k = 0; k < 32; k++) {
                int n = nl + 8 * k;
                float pv = SC[st * NTOK + n];
                #pragma unroll
                for (int d = 0; d < DH; d++)
                    part[d] = fmaf(pv, KV[d * NTOK + n], part[d]);
            }
            #pragma unroll
            for (int d = 0; d < DH; d++) {
                part[d] += __shfl_xor_sync(0xffffffffu, part[d], 1);
                part[d] += __shfl_xor_sync(0xffffffffu, part[d], 2);
                part[d] += __shfl_xor_sync(0xffffffffu, part[d], 4);
            }
            #pragma unroll
            for (int m2 = 0; m2 < 4; m2++) {
                int d = nl * 4 + m2;
                AO[(h * DH + d) * ST + st] = part[d];
            }
        }
        __syncthreads();
    }

    {   // proj + gated residual -> g_f
        ull acc2[4][4] = {};
        gemm_block<256, 128>(projw, AO, W2, acc2);
        float* gf = g_f + (size_t)b * QCH * STOT + s0;
        #pragma unroll
        for (int p = 0; p < 4; p++) {
            int ra = r0 + 64 * p, rb = ra + 32;
            float ba = projb[ra], bb = projb[rb];
            #pragma unroll
            for (int j = 0; j < 4; j++) {
                float lo, hi; unpack2(acc2[p][j], lo, hi);
                gf[(size_t)ra * STOT + c0 + j] = F[ra * ST + c0 + j] + tg * (lo + ba);
                gf[(size_t)rb * STOT + c0 + j] = F[rb * ST + c0 + j] + tg * (hi + bb);
            }
        }
    }
}

// ===========================================================================
// FF kernel via mma.sync fp16, 3 CTAs/SM, M-tile 32, warp tile 32x32
// (1M x 8N over 256-n units), k16-granular 8KB W slots, static unrolling,
// single __syncthreads per unit.  0.5 ldsm per MMA.  R17: weights are
// unit-contiguous + pre-swizzled in global, so staging is a flat coalesced
// 8KB copy (thread tid copies bytes [tid*32, tid*32+32)).
// out = src + FF2(silu(FF1(src)+b1)) + b2
// SMEM (64KB/CTA -> 3 resident CTAs):
//   X[32][256] fp16 @0 (16KB), H[32][512] fp16 @16384 (32KB),
//   W double buffers @49152 (2 x 8KB = 256 rows x 32B each).
// X/H swizzle: 16B atom index ^= (row & 7).
// W-slot swizzle (32B rows, 2 atoms): atom ^= (row>>2) & 1 (pre-baked).
// ===========================================================================
#define SM_H  16384u
#define SM_W  49152u
#define SMEM_FF 65536

__global__ void __launch_bounds__(256, 3)
ff_mma_kernel(const float* __restrict__ feat,
              const float* __restrict__ ff1b, const float* __restrict__ ff2b,
              const float* __restrict__ gate, float* __restrict__ out)
{
    extern __shared__ char smc[];
    const uint32_t sb = smem_u32(smc);
    const int tid  = threadIdx.x;
    const int wid  = tid >> 5, lane = tid & 31;
    const int g    = lane >> 2, tg = lane & 3;
    const int q    = lane >> 3, r8 = lane & 7;
    const int b    = blockIdx.y;
    const int s0   = blockIdx.x * 32;

    const float* src  = (gate[0] == 0.0f) ? feat : (const float*)g_f;
    const float* srcb = src + (size_t)b * QCH * STOT + s0;
    float*       outb = out + (size_t)b * QCH * STOT + s0;

    // ---- staging geometry: flat contiguous 8KB copy ----
    const uint32_t dstOff0 = sb + SM_W + (uint32_t)tid * 32u;
    const char* w1src = (const char*)g_w1h + (uint32_t)tid * 32u;   // + unit*8192
    const char* w2src = (const char*)g_w2h + (uint32_t)tid * 32u;   // + ko*8192

    // ---- preload weight unit 0 (FF1 nch0 kh0) ----
    cp16(dstOff0, w1src);
    cp16(dstOff0 + 16u, w1src + 16);
    asm volatile("cp.async.commit_group;");

    // ---- X convert: src[c][s0+m] -> X[m][k=c] fp16, swizzled ----
    {
        const int c = tid;
        const float* row = srcb + (size_t)c * STOT;
        const uint32_t katom  = (uint32_t)c >> 3;
        const uint32_t inatom = ((uint32_t)c * 2) & 15;
        #pragma unroll
        for (int s4 = 0; s4 < 32; s4 += 4) {
            float4 v = *(const float4*)(row + s4);
            float vv[4] = {v.x, v.y, v.z, v.w};
            #pragma unroll
            for (int e = 0; e < 4; e++) {
                int m = s4 + e;
                uint32_t off = (uint32_t)m * 512u + ((katom ^ (uint32_t)(m & 7)) << 4) + inatom;
                *(__half*)(smc + off) = __float2half(vv[e]);
            }
        }
    }

    // ---- ldsm geometry ----
    const int aRow  = (q & 1) * 8 + r8;            // rows 0..15; fC at +16
    const int aQk   = q >> 1;
    const uint32_t r7A   = (uint32_t)(aRow & 7);
    const uint32_t aBit0 = ((uint32_t)aQk ^ (r7A & 1)) << 4;
    const uint32_t r7hi  = r7A >> 1;               // 2 bits, XORed with k index
    const uint32_t aBX = sb + (uint32_t)aRow * 512u + aBit0;
    const uint32_t aBH = sb + SM_H + (uint32_t)aRow * 1024u + aBit0;
    const int bRow = wid * 32 + (q >> 1) * 8 + r8;
    const uint32_t bA0 = sb + SM_W + (uint32_t)bRow * 32u
                       + (((uint32_t)(q & 1) ^ ((uint32_t)(bRow >> 2) & 1)) << 4);
    // second B matrix at row+16: (row>>2)&1 flips? (bRow+16)>>2 = bRow>>2+4,
    // bit0 unchanged -> +512 bytes only.

    float acc[2][4][4];

    // =================== FF1 phase (2 nch x 16 kh units) ==================
    #pragma unroll 1
    for (int nch = 0; nch < 2; nch++) {
        #pragma unroll
        for (int mt = 0; mt < 2; mt++)
            #pragma unroll
            for (int nt = 0; nt < 4; nt++)
                #pragma unroll
                for (int j = 0; j < 4; j++) acc[mt][nt][j] = 0.f;

        const char* wnb = w1src + nch * 131072;     // 16 units x 8KB

        #pragma unroll
        for (int kh = 0; kh < 16; kh++) {
            asm volatile("cp.async.wait_group 0;" ::: "memory");
            __syncthreads();   // publish slot kh&1; separate stage/compute

            if (kh < 15) {
                const uint32_t db = dstOff0 + (uint32_t)(((kh + 1) & 1) * 8192);
                cp16(db, wnb + (kh + 1) * 8192);
                cp16(db + 16u, wnb + (kh + 1) * 8192 + 16);
            } else if (nch == 0) {
                cp16(dstOff0, wnb + 131072);
                cp16(dstOff0 + 16u, wnb + 131072 + 16);
            } else {
                cp16(dstOff0, w2src);
                cp16(dstOff0 + 16u, w2src + 16);
            }
            asm volatile("cp.async.commit_group;");

            const uint32_t slotOff = (uint32_t)((kh & 1) * 8192);
            const uint32_t aA = aBX + (((uint32_t)kh ^ r7hi) << 5);
            const uint32_t bAdr = bA0 + slotOff;

            uint32_t fA[4], fC[4], fB0[4], fB1[4];
            ldsm4(fA[0], fA[1], fA[2], fA[3], aA);
            ldsm4(fC[0], fC[1], fC[2], fC[3], aA + 8192u);
            ldsm4(fB0[0], fB0[1], fB0[2], fB0[3], bAdr);
            ldsm4(fB1[0], fB1[1], fB1[2], fB1[3], bAdr + 512u);
            mma16816(acc[0][0], fA, fB0[0], fB0[1]);
            mma16816(acc[0][1], fA, fB0[2], fB0[3]);
            mma16816(acc[0][2], fA, fB1[0], fB1[1]);
            mma16816(acc[0][3], fA, fB1[2], fB1[3]);
            mma16816(acc[1][0], fC, fB0[0], fB0[1]);
            mma16816(acc[1][1], fC, fB0[2], fB0[3]);
            mma16816(acc[1][2], fC, fB1[0], fB1[1]);
            mma16816(acc[1][3], fC, fB1[2], fB1[3]);
        }

        // epilogue: bias + silu -> H fp16 (swizzled, 64 atoms/row)
        #pragma unroll
        for (int nt = 0; nt < 4; nt++) {
            int cg = nch * 256 + wid * 32 + nt * 8 + tg * 2;
            float b1v = __ldg(ff1b + cg);
            float b2v = __ldg(ff1b + cg + 1);
            uint32_t katom = (uint32_t)(cg >> 3);
            uint32_t inb   = ((uint32_t)cg * 2) & 15;
            #pragma unroll
            for (int mt = 0; mt < 2; mt++) {
                int m0 = mt * 16 + g;
                float x0 = acc[mt][nt][0] + b1v;
                float x1 = acc[mt][nt][1] + b2v;
                float x2 = acc[mt][nt][2] + b1v;
                float x3 = acc[mt][nt][3] + b2v;
                float h0 = x0 / (1.0f + __expf(-x0));
                float h1 = x1 / (1.0f + __expf(-x1));
                float h2 = x2 / (1.0f + __expf(-x2));
                float h3 = x3 / (1.0f + __expf(-x3));
                uint32_t off0 = SM_H + (uint32_t)m0 * 1024u + ((katom ^ (uint32_t)(m0 & 7)) << 4) + inb;
                uint32_t off1 = SM_H + (uint32_t)(m0 + 8) * 1024u + ((katom ^ (uint32_t)((m0 + 8) & 7)) << 4) + inb;
                *(__half2*)(smc + off0) = __floats2half2_rn(h0, h1);
                *(__half2*)(smc + off1) = __floats2half2_rn(h2, h3);
            }
        }
    }

    // =================== FF2 phase (32 ko units, acc persists) ============
    #pragma unroll
    for (int mt = 0; mt < 2; mt++)
        #pragma unroll
        for (int nt = 0; nt < 4; nt++)
            #pragma unroll
            for (int j = 0; j < 4; j++) acc[mt][nt][j] = 0.f;

    #pragma unroll
    for (int ko = 0; ko < 32; ko++) {
        asm volatile("cp.async.wait_group 0;" ::: "memory");
        __syncthreads();

        if (ko < 31) {
            const uint32_t db = dstOff0 + (uint32_t)(((ko + 1) & 1) * 8192);
            cp16(db, w2src + (ko + 1) * 8192);
            cp16(db + 16u, w2src + (ko + 1) * 8192 + 16);
            asm volatile("cp.async.commit_group;");
        }

        const uint32_t slotOff = (uint32_t)((ko & 1) * 8192);
        const uint32_t aA = aBH + (((uint32_t)ko ^ r7hi) << 5);
        const uint32_t bAdr = bA0 + slotOff;

        uint32_t fA[4], fC[4], fB0[4], fB1[4];
        ldsm4(fA[0], fA[1], fA[2], fA[3], aA);
        ldsm4(fC[0], fC[1], fC[2], fC[3], aA + 16384u);
        ldsm4(fB0[0], fB0[1], fB0[2], fB0[3], bAdr);
        ldsm4(fB1[0], fB1[1], fB1[2], fB1[3], bAdr + 512u);
        mma16816(acc[0][0], fA, fB0[0], fB0[1]);
        mma16816(acc[0][1], fA, fB0[2], fB0[3]);
        mma16816(acc[0][2], fA, fB1[0], fB1[1]);
        mma16816(acc[0][3], fA, fB1[2], fB1[3]);
        mma16816(acc[1][0], fC, fB0[0], fB0[1]);
        mma16816(acc[1][1], fC, fB0[2], fB0[3]);
        mma16816(acc[1][2], fC, fB1[0], fB1[1]);
        mma16816(acc[1][3], fC, fB1[2], fB1[3]);
    }

    // FF2 epilogue: D = 32m x 256c; four 64-channel passes via Xf [64c][36m]
    {
        float* Xf = (float*)smc;
        #pragma unroll
        for (int p = 0; p < 4; p++) {
            __syncthreads();
            if ((wid >> 1) == p) {
                #pragma unroll
                for (int nt = 0; nt < 4; nt++) {
                    int cc = (wid & 1) * 32 + nt * 8 + tg * 2;
                    #pragma unroll
                    for (int mt = 0; mt < 2; mt++) {
                        int m0 = mt * 16 + g;
                        Xf[cc * 36 + m0]           = acc[mt][nt][0];
                        Xf[(cc + 1) * 36 + m0]     = acc[mt][nt][1];
                        Xf[cc * 36 + m0 + 8]       = acc[mt][nt][2];
                        Xf[(cc + 1) * 36 + m0 + 8] = acc[mt][nt][3];
                    }
                }
            }
            __syncthreads();
            {
                int cc = tid >> 2, ms = (tid & 3) * 8;
                int cg = p * 64 + cc;
                float bias = __ldg(ff2b + cg);
                const float* sr = srcb + (size_t)cg * STOT + ms;
                float* ob = outb + (size_t)cg * STOT + ms;
                #pragma unroll
                for (int j = 0; j < 2; j++) {
                    float4 rv = *(const float4*)(sr + 4 * j);
                    float4 o;
                    o.x = Xf[cc * 36 + ms + 4 * j + 0] + bias + rv.x;
                    o.y = Xf[cc * 36 + ms + 4 * j + 1] + bias + rv.y;
                    o.z = Xf[cc * 36 + ms + 4 * j + 2] + bias + rv.z;
                    o.w = Xf[cc * 36 + ms + 4 * j + 3] + bias + rv.w;
                    *(float4*)(ob + 4 * j) = o;
                }
            }
        }
    }
}

extern "C" void kernel_launch(void* const* d_in, const int* in_sizes, int n_in,
                              void* d_out, int out_size)
{
    const float* feat   = (const float*)d_in[0];
    const float* tokens = (const float*)d_in[1];
    const float* qw     = (const float*)d_in[2];
    const float* qb     = (const float*)d_in[3];
    const float* kw     = (const float*)d_in[4];
    const float* vw     = (const float*)d_in[5];
    const float* projw  = (const float*)d_in[6];
    const float* projb  = (const float*)d_in[7];
    const float* ff1w   = (const float*)d_in[8];
    const float* ff1b   = (const float*)d_in[9];
    const float* ff2w   = (const float*)d_in[10];
    const float* ff2b   = (const float*)d_in[11];
    const float* gate   = (const float*)d_in[12];
    float* out = (float*)d_out;

    cudaFuncSetAttribute(attn_kernel, cudaFuncAttributeMaxDynamicSharedMemorySize, 131072);
    cudaFuncSetAttribute(ff_mma_kernel, cudaFuncAttributeMaxDynamicSharedMemorySize, SMEM_FF);

    prep_kernel<<<512, 256>>>(ff1w, ff2w);
    kv_kernel<<<NB * NTOK, 128>>>(tokens, kw, vw, gate);
    attn_kernel<<<dim3(STOT / ST, NB), 256, 131072>>>(feat, qw, qb, projw, projb, gate);
    ff_mma_kernel<<<dim3(STOT / 32, NB), 256, SMEM_FF>>>(feat, ff1b, ff2b, gate, out);
}